// round 17
// baseline (speedup 1.0000x reference)
#include <cuda_runtime.h>
#include <cmath>

// ---------------------------------------------------------------------------
// Mann eddy-lifetime tau(k) = TS * (L|k|)^(-2/3) / sqrt(2F1(1/3,17/6,4/3,-(L|k|)^-2))
//
// s = (L|k|)^2, branch split at s = 1/PHI:
//   Branch A (s >= 1/PHI):  tau = rsqrt(s * S_A(w)) * w^(-1/6),  w = 1/(1+s)
//   Branch B (s <  1/PHI):  tau = rsqrt(A*s + B*s^(7/2) * S_B(-s))
// Series Taylor-expanded about the center of their argument ranges (+-0.309),
// NT=8 (measured rel_err 1.47e-7). TS folded into rsqrt arg; B=-2/15 folded
// into S_B coeffs. Dual series via packed fma.rn.f32x2; shared lg2/ex2 pair.
//
// R17: COALESCED LOADS via smem staging. The direct AoS pattern (thread t
// loads float4 3t,3t+1,3t+2) makes each LDG.128 span 12 cache lines/warp
// (48B stride) -> 36 L1tex wavefronts per warp-tile. Staging through smem
// makes every LDG.128 span the minimum 4 lines (12 wavefronts), cutting
// L1tex queue occupancy 3x. Compute body and stores unchanged from the
// proven-best R6 configuration (EPT=4, block 256, 3xLDG.128+1xSTG.128).
// ---------------------------------------------------------------------------

#define NT 8
#define EPT 4    // elements per thread
#define BLK 256  // threads per block

static constexpr float  S0F   = 0.6180339887498949f;    // 1/PHI
static constexpr double W0    = 0.30901699437494745;    // expansion center
static constexpr float  W0F   = (float)W0;
static constexpr double SCALE = 1.0 / (3.9 * 3.9);      // fold TS into rsqrt arg

__host__ __device__ constexpr double hyp2f1_cx(double a, double b, double c, double z) {
    double s = 1.0, t = 1.0;
    for (int n = 0; n < 220; ++n) {
        t *= (a + n) * (b + n) / ((c + n) * (n + 1.0)) * z;
        s += t;
    }
    return s;
}

// m-th shifted Taylor coefficient of 2F1(a,b,c,.) about z0, times 'mul'.
__host__ __device__ constexpr float shifted_coef(double a, double b, double c,
                                                 double z0, int m, double mul) {
    double p = 1.0;
    for (int i = 0; i < m; ++i)
        p *= (a + i) * (b + i) / ((c + i) * (i + 1.0));
    return (float)(p * hyp2f1_cx(a + m, b + m, c + m, z0) * mul);
}

__host__ __device__ constexpr float coefA(int m) {
    return shifted_coef(1.0 / 3.0, -1.5, 4.0 / 3.0, W0, m, SCALE);
}
__host__ __device__ constexpr float coefB(int m) {
    return shifted_coef(17.0 / 6.0, 2.5, 3.5, -W0, m, (-2.0 / 15.0) * SCALE);
}

// Packed dual Horner step: acc = acc * z + {cA, cB}; EPT independent chains.
template <int I>
__device__ __forceinline__ void horner_step(const unsigned long long z[EPT],
                                            unsigned long long acc[EPT]) {
    constexpr float cA = coefA(I);
    constexpr float cB = coefB(I);
    unsigned long long cP;
    asm("mov.b64 %0, {%1, %2};" : "=l"(cP) : "f"(cA), "f"(cB));
#pragma unroll
    for (int j = 0; j < EPT; ++j)
        asm("fma.rn.f32x2 %0, %0, %1, %2;" : "+l"(acc[j]) : "l"(z[j]), "l"(cP));
    if constexpr (I > 0) horner_step<I - 1>(z, acc);
}

__device__ __forceinline__ float rcp_approx(float x) {
    float r; asm("rcp.approx.f32 %0, %1;" : "=f"(r) : "f"(x)); return r;
}
__device__ __forceinline__ float ex2_approx(float x) {
    float r; asm("ex2.approx.f32 %0, %1;" : "=f"(r) : "f"(x)); return r;
}
__device__ __forceinline__ float lg2_approx(float x) {
    float r; asm("lg2.approx.f32 %0, %1;" : "=f"(r) : "f"(x)); return r;
}

__global__ void __launch_bounds__(BLK)
mann_elt_kernel(const float* __restrict__ k, float* __restrict__ out,
                float Aprime, int n4) {
    __shared__ float4 stage[3 * BLK];   // 12 KB: this block's 3072 floats

    int t = threadIdx.x;
    int i = blockIdx.x * BLK + t;       // output float4 index (= element/4)

    // --- Coalesced staging: 3 x LDG.128, each spanning 4 lines per warp ---
    const float4* kb = reinterpret_cast<const float4*>(k) + 3 * (long)blockIdx.x * BLK;
    stage[t          ] = __ldcs(kb + t);
    stage[t +     BLK] = __ldcs(kb + t + BLK);
    stage[t + 2 * BLK] = __ldcs(kb + t + 2 * BLK);
    __syncthreads();

    // --- Per-thread AoS read from smem (cheap; no DRAM involvement) ---
    float4 v0 = stage[3 * t + 0];
    float4 v1 = stage[3 * t + 1];
    float4 v2 = stage[3 * t + 2];

    float kx[EPT] = {v0.x, v0.w, v1.z, v2.y};
    float ky[EPT] = {v0.y, v1.x, v1.w, v2.z};
    float kz[EPT] = {v0.z, v1.y, v2.x, v2.w};

    const float L2 = 0.59f * 0.59f;

    float s[EPT], w[EPT];
    unsigned long long z[EPT], acc[EPT];
    unsigned long long accInit;
    {
        constexpr float tA = coefA(NT - 1);
        constexpr float tB = coefB(NT - 1);
        asm("mov.b64 %0, {%1, %2};" : "=l"(accInit) : "f"(tA), "f"(tB));
    }
#pragma unroll
    for (int j = 0; j < EPT; ++j) {
        float d = fmaf(kx[j], kx[j], fmaf(ky[j], ky[j], kz[j] * kz[j]));
        s[j] = L2 * d;
        // w = 1/(1 + max(s, 1/PHI)) in (0, 0.618]; shifted arg zA = w - 0.309
        w[j] = rcp_approx(1.0f + fmaxf(s[j], S0F));
        float zA = w[j] - W0F;
        // u = -min(s, 1/PHI); shifted arg zB = u + 0.309
        float zB = fmaxf(W0F - s[j], -W0F);
        asm("mov.b64 %0, {%1, %2};" : "=l"(z[j]) : "f"(zA), "f"(zB));
        acc[j] = accInit;
    }

    horner_step<NT - 2>(z, acc);

    float r[EPT];
#pragma unroll
    for (int j = 0; j < EPT; ++j) {
        float sA, sB;
        asm("mov.b64 {%0, %1}, %2;" : "=f"(sA), "=f"(sB) : "l"(acc[j]));
        float ss = s[j];
        bool  bA = (ss >= S0F);
        // Shared MUFU pair: branch A -> e = w^(-1/6); branch B -> e = sqrt(s).
        float y  = bA ? w[j] : ss;
        float pw = bA ? (-1.0f / 6.0f) : 0.5f;
        float e  = ex2_approx(lg2_approx(y) * pw);
        // Branch A: arg = s * S_A'
        float argA = ss * sA;
        // Branch B: arg = s * (A' + s^2 * sqrt(s) * S_B')
        float argB = ss * fmaf(ss * ss * e, sB, Aprime);
        float arg  = bA ? argA : argB;
        float m    = bA ? e : 1.0f;
        r[j] = rsqrtf(arg) * m;
    }

    float4 o = make_float4(r[0], r[1], r[2], r[3]);
    __stcs(&reinterpret_cast<float4*>(out)[i], o);
}

extern "C" void kernel_launch(void* const* d_in, const int* in_sizes, int n_in,
                              void* d_out, int out_size) {
    const float* k = (const float*)d_in[0];
    float* out = (float*)d_out;

    // A = G(4/3)G(5/2)/G(17/6); folded with SCALE = 1/3.9^2.
    double Ad = std::tgamma(4.0 / 3.0) * std::tgamma(2.5) / std::tgamma(17.0 / 6.0);
    float Aprime = (float)(Ad * SCALE);

    int n  = in_sizes[0] / 3;
    int n4 = n / EPT;   // n = 256^3, divisible by 4; n4 divisible by BLK

    int blocks = n4 / BLK;
    mann_elt_kernel<<<blocks, BLK>>>(k, out, Aprime, n4);
}